// round 12
// baseline (speedup 1.0000x reference)
#include <cuda_runtime.h>
#include <cstdint>

// RWKV7 WKV — chunked UT-transform, L=16 (v5).
// k1: per (chunk,head) precompute (parallel, 8192 CTAs) + transposed V export.
// k2: serial over chunks, 128 CTAs x 512 threads (4 warps/SMSP);
//     warp-sliced 64-wide streams, broadcast 16x16 matrices,
//     G/U/V stored transposed so all small-matrix reads are float4-contiguous.

#define HH 32
#define NN 64
#define L  16
#define NCMAX 256

typedef unsigned long long u64;

__device__ float g_At [NCMAX*HH*L*NN];
__device__ float g_Rt [NCMAX*HH*L*NN];
__device__ float g_Bh [NCMAX*HH*L*NN];
__device__ float g_Kh [NCMAX*HH*L*NN];
__device__ float g_MV [NCMAX*HH*L*NN];
__device__ float g_RKV[NCMAX*HH*L*NN];
__device__ float g_Vt [NCMAX*HH*NN*L];   // [c][h][i][s]
__device__ float g_Ti [NCMAX*HH*L*L];
__device__ float g_RB [NCMAX*HH*L*L];
__device__ float g_wL [NCMAX*HH*NN];

__device__ __forceinline__ u64 fma2(u64 a, u64 b, u64 c) {
    u64 d; asm("fma.rn.f32x2 %0, %1, %2, %3;" : "=l"(d) : "l"(a), "l"(b), "l"(c)); return d;
}
__device__ __forceinline__ u64 add2(u64 a, u64 b) {
    u64 d; asm("add.rn.f32x2 %0, %1, %2;" : "=l"(d) : "l"(a), "l"(b)); return d;
}
__device__ __forceinline__ u64 mul2(u64 a, u64 b) {
    u64 d; asm("mul.rn.f32x2 %0, %1, %2;" : "=l"(d) : "l"(a), "l"(b)); return d;
}
__device__ __forceinline__ u64 bcast2(float x) {
    u64 d; asm("mov.b64 %0, {%1, %1};" : "=l"(d) : "f"(x)); return d;
}
__device__ __forceinline__ float hsum2(u64 a) {
    float x, y; asm("mov.b64 {%0, %1}, %2;" : "=f"(x), "=f"(y) : "l"(a)); return x + y;
}
__device__ __forceinline__ void cp_async16(void* smem_dst, const void* gsrc) {
    unsigned saddr = (unsigned)__cvta_generic_to_shared(smem_dst);
    asm volatile("cp.async.ca.shared.global [%0], [%1], 16;\n"
                 :: "r"(saddr), "l"(gsrc) : "memory");
}

// ================= kernel 1: per-chunk precompute (parallel) ===============
__global__ __launch_bounds__(128)
void wkv7_k1(const float* __restrict__ rP, const float* __restrict__ wP,
             const float* __restrict__ kP, const float* __restrict__ vP,
             const float* __restrict__ aP, const float* __restrict__ bP)
{
    const int c = blockIdx.x >> 5, h = blockIdx.x & 31, tid = threadIdx.x;

    __shared__ float sW[L][68], sA[L][68], sB[L][68], sK[L][68], sR[L][68], sV[L][68];
    __shared__ float sC[L][17], sM[L][17], sRBm[L][17], sRKm[L][17], sTi[L][17];

    for (int idx = tid; idx < L*NN; idx += 128) {
        int tau = idx >> 6, j = idx & 63;
        size_t g = ((size_t)(c*L + tau) * HH + h) * NN + j;
        sW[tau][j] = fmaxf(wP[g], 1e-9f);
        sA[tau][j] = aP[g]; sB[tau][j] = bP[g]; sK[tau][j] = kP[g];
        sR[tau][j] = rP[g]; sV[tau][j] = vP[g];
    }
    __syncthreads();

    if (tid < NN) {
        float run = 1.f;
        #pragma unroll
        for (int tau = 0; tau < L; ++tau) { run *= sW[tau][tid]; sW[tau][tid] = run; }
    }
    __syncthreads();

    for (int idx = tid; idx < L*NN; idx += 128) {
        int tau = idx >> 6, j = idx & 63;
        float Wc = sW[tau][j];
        float Wp = tau ? sW[tau-1][j] : 1.f;
        float inv = 1.f / Wc;
        sA[tau][j] *= Wp; sB[tau][j] *= inv; sK[tau][j] *= inv; sR[tau][j] *= Wc;
    }
    __syncthreads();

    {
        const int s = tid & 15;
        const int tau1 = tid >> 4, tau2 = tau1 + 8;
        const u64* Bp = (const u64*)&sB[s][0];
        const u64* Kp = (const u64*)&sK[s][0];
        const u64* A1 = (const u64*)&sA[tau1][0];
        const u64* R1 = (const u64*)&sR[tau1][0];
        const u64* A2 = (const u64*)&sA[tau2][0];
        const u64* R2 = (const u64*)&sR[tau2][0];
        u64 c1=0,m1=0,rb1=0,rk1=0, c2=0,m2=0,rb2=0,rk2=0;
        #pragma unroll 8
        for (int p = 0; p < 32; ++p) {
            u64 bs = Bp[p], ks = Kp[p];
            u64 a1 = A1[p], r1 = R1[p], a2 = A2[p], r2 = R2[p];
            c1 = fma2(a1, bs, c1);  m1 = fma2(a1, ks, m1);
            rb1 = fma2(r1, bs, rb1); rk1 = fma2(r1, ks, rk1);
            c2 = fma2(a2, bs, c2);  m2 = fma2(a2, ks, m2);
            rb2 = fma2(r2, bs, rb2); rk2 = fma2(r2, ks, rk2);
        }
        float fc1=hsum2(c1), fm1=hsum2(m1), frb1=hsum2(rb1), frk1=hsum2(rk1);
        float fc2=hsum2(c2), fm2=hsum2(m2), frb2=hsum2(rb2), frk2=hsum2(rk2);
        if (s >  tau1) { frb1 = 0.f; frk1 = 0.f; }
        if (s >= tau1) { fc1 = 0.f;  fm1 = 0.f; }
        if (s >  tau2) { frb2 = 0.f; frk2 = 0.f; }
        if (s >= tau2) { fc2 = 0.f;  fm2 = 0.f; }
        sC[tau1][s]=fc1; sM[tau1][s]=fm1; sRBm[tau1][s]=frb1; sRKm[tau1][s]=frk1;
        sC[tau2][s]=fc2; sM[tau2][s]=fm2; sRBm[tau2][s]=frb2; sRKm[tau2][s]=frk2;
    }
    __syncthreads();

    if (tid < L) {
        const int s = tid;
        for (int tau = 0; tau < L; ++tau) {
            float x = (tau == s) ? 1.f : 0.f;
            for (int u = s; u < tau; ++u) x = fmaf(sC[tau][u], sTi[u][s], x);
            sTi[tau][s] = (tau >= s) ? x : 0.f;
        }
    }
    __syncthreads();

    const size_t LN = ((size_t)c*HH + h) * (L*NN);

    #pragma unroll
    for (int g2 = 0; g2 < 2; ++g2) {
        int grp = tid + g2*128;
        int tau = grp >> 4, i4 = (grp & 15) * 4;
        u64 mv0=0, mv1=0, rk0=0, rk1=0;
        #pragma unroll
        for (int s = 0; s < L; ++s) {
            const u64* vp = (const u64*)&sV[s][i4];
            u64 v0 = vp[0], v1 = vp[1];
            u64 m2b = bcast2(sM[tau][s]);
            u64 k2b = bcast2(sRKm[tau][s]);
            mv0 = fma2(m2b, v0, mv0); mv1 = fma2(m2b, v1, mv1);
            rk0 = fma2(k2b, v0, rk0); rk1 = fma2(k2b, v1, rk1);
        }
        u64* od = (u64*)(g_MV + LN + tau*NN + i4);
        od[0] = mv0; od[1] = mv1;
        u64* od2 = (u64*)(g_RKV + LN + tau*NN + i4);
        od2[0] = rk0; od2[1] = rk1;
    }

    for (int idx = tid; idx < L*NN; idx += 128) {
        int tau = idx >> 6, j = idx & 63;
        float wl = sW[L-1][j];
        g_At[LN+idx] = sA[tau][j];
        g_Rt[LN+idx] = sR[tau][j];
        g_Bh[LN+idx] = sB[tau][j] * wl;
        g_Kh[LN+idx] = sK[tau][j] * wl;
    }
    // transposed V: [i][s]
    const size_t VT = ((size_t)c*HH + h) * (NN*L);
    for (int idx = tid; idx < NN*L; idx += 128) {
        int i = idx >> 4, s = idx & 15;
        g_Vt[VT + idx] = sV[s][i];
    }
    const size_t Tb = ((size_t)c*HH + h) * (L*L);
    for (int idx = tid; idx < 256; idx += 128) {
        g_Ti[Tb+idx] = sTi[idx>>4][idx&15];
        g_RB[Tb+idx] = sRBm[idx>>4][idx&15];
    }
    if (tid < NN) g_wL[((size_t)c*HH + h)*NN + tid] = sW[L-1][tid];
}

// ================= kernel 2: serial over chunks (512 threads) ==============
struct Stage {
    float Aq[L][68], Rq[L][68], Bq[L][68], Kq[L][68];
    float Ti[L][20], RBm[L][20];
    float MV[L][16], RKV[L][16];
    float Vt[16][16];       // [ii][s]
    float wL[64];
};
#define STAGE_F ((int)(sizeof(Stage)/4))

__device__ __forceinline__ void loadStage(Stage& st, int c, int h, int i0, int tid)
{
    const size_t LN = ((size_t)c*HH + h) * (L*NN);
    const size_t Tb = ((size_t)c*HH + h) * (L*L);
    const size_t VT = ((size_t)c*HH + h) * (NN*L);

    if (tid < 256) {
        int row = tid >> 4, q = (tid & 15) * 4;
        cp_async16(&st.Aq[row][q], g_At + LN + row*NN + q);
        cp_async16(&st.Rq[row][q], g_Rt + LN + row*NN + q);
    } else {
        int t = tid & 255;
        int row = t >> 4, q = (t & 15) * 4;
        cp_async16(&st.Bq[row][q], g_Bh + LN + row*NN + q);
        cp_async16(&st.Kq[row][q], g_Kh + LN + row*NN + q);
    }
    if (tid < 64) {
        int row = tid >> 2, q = (tid & 3) * 4;
        cp_async16(&st.Ti[row][q], g_Ti + Tb + row*L + q);
    } else if (tid < 128) {
        int e = tid - 64, row = e >> 2, q = (e & 3) * 4;
        cp_async16(&st.RBm[row][q], g_RB + Tb + row*L + q);
    } else if (tid < 192) {
        int e = tid - 128, row = e >> 2, q = (e & 3) * 4;
        cp_async16(&st.MV[row][q], g_MV + LN + row*NN + i0 + q);
    } else if (tid < 256) {
        int e = tid - 192, row = e >> 2, q = (e & 3) * 4;
        cp_async16(&st.RKV[row][q], g_RKV + LN + row*NN + i0 + q);
    } else if (tid < 320) {
        int e = tid - 256, ii = e >> 2, q = (e & 3) * 4;
        cp_async16(&st.Vt[ii][q], g_Vt + VT + (size_t)(i0 + ii)*L + q);
    } else if (tid < 336) {
        int e = tid - 320;
        cp_async16(&st.wL[e*4], g_wL + ((size_t)c*HH + h)*NN + e*4);
    }
}

__global__ __launch_bounds__(512, 1)
void wkv7_k2(const float* __restrict__ stateP,
             float* __restrict__ yOut, float* __restrict__ sOut, int NC)
{
    extern __shared__ float dyn[];
    Stage* st  = (Stage*)dyn;
    float* sS  = dyn + 3*STAGE_F;        // [16][68]
    float* sGt = sS + 16*68;             // [16][20]  (ii, tau)
    float* sUt = sGt + 16*20;            // [16][20]  (ii, tau)
    float* sY  = sUt + 16*20;            // [16][17]  (tau, ii)

    const int tid = threadIdx.x;
    const int h  = blockIdx.x >> 2, sl = blockIdx.x & 3;
    const int i0 = sl * 16;

    const int warp = tid >> 5, lane = tid & 31;
    // stage 1: warp pair covers 2 taus x 8 ii; lanes = (iiL:8, jh:4)
    const int iiL  = lane & 7, jh = lane >> 3;
    const int tauA = (warp >> 1) * 2, tauB = tauA + 1;
    const int ii1  = ((warp & 1) * 8) + iiL;
    // U / Y-finalize: warp = tau; lanes 0..15 = ii (upper half duplicates)
    const int tauU = warp, iiU = lane & 15;
    // S-update: warp owns j in [warp*4, warp*4+4); lanes = (iiS:16, half:2)
    const int jb  = warp*4 + (lane >> 4)*2;
    const int iiS = lane & 15;

    // ---- state into SMEM ----
    #pragma unroll
    for (int r = 0; r < 2; ++r) {
        int idx = tid + r*512;
        int si = idx >> 6, j = idx & 63;
        sS[si*68 + j] = stateP[((size_t)h*NN + i0 + si)*NN + j];
    }

    if (NC > 0) loadStage(st[0], 0, h, i0, tid);
    asm volatile("cp.async.commit_group;\n" ::: "memory");
    if (NC > 1) loadStage(st[1], 1, h, i0, tid);
    asm volatile("cp.async.commit_group;\n" ::: "memory");

    #pragma unroll 1
    for (int c = 0; c < NC; ++c) {
        asm volatile("cp.async.wait_group 1;\n" ::: "memory");
        __syncthreads();
        if (c + 2 < NC) loadStage(st[(c+2)%3], c+2, h, i0, tid);
        asm volatile("cp.async.commit_group;\n" ::: "memory");

        Stage& S = st[c % 3];

        // ---- stage 1: G = A~ . S, Y0 = R~ . S (j sliced by jh) ----
        {
            u64 g0=0, g1=0, q0=0, q1=0;
            #pragma unroll
            for (int p = 0; p < 4; ++p) {
                const int jo = p*16 + jh*4;
                ulonglong2 sv = *(const ulonglong2*)&sS[ii1*68 + jo];
                ulonglong2 a0 = *(const ulonglong2*)&S.Aq[tauA][jo];
                ulonglong2 a1 = *(const ulonglong2*)&S.Aq[tauB][jo];
                ulonglong2 r0 = *(const ulonglong2*)&S.Rq[tauA][jo];
                ulonglong2 r1 = *(const ulonglong2*)&S.Rq[tauB][jo];
                g0 = fma2(a0.x, sv.x, g0); g0 = fma2(a0.y, sv.y, g0);
                g1 = fma2(a1.x, sv.x, g1); g1 = fma2(a1.y, sv.y, g1);
                q0 = fma2(r0.x, sv.x, q0); q0 = fma2(r0.y, sv.y, q0);
                q1 = fma2(r1.x, sv.x, q1); q1 = fma2(r1.y, sv.y, q1);
            }
            float fg0 = hsum2(g0), fg1 = hsum2(g1);
            float fy0 = hsum2(q0), fy1 = hsum2(q1);
            fg0 += __shfl_xor_sync(0xffffffffu, fg0, 8);
            fg1 += __shfl_xor_sync(0xffffffffu, fg1, 8);
            fy0 += __shfl_xor_sync(0xffffffffu, fy0, 8);
            fy1 += __shfl_xor_sync(0xffffffffu, fy1, 8);
            fg0 += __shfl_xor_sync(0xffffffffu, fg0, 16);
            fg1 += __shfl_xor_sync(0xffffffffu, fg1, 16);
            fy0 += __shfl_xor_sync(0xffffffffu, fy0, 16);
            fy1 += __shfl_xor_sync(0xffffffffu, fy1, 16);
            if (jh == 0) {
                sGt[ii1*20 + tauA] = fg0 + S.MV[tauA][ii1];
                sGt[ii1*20 + tauB] = fg1 + S.MV[tauB][ii1];
                sY[tauA*17 + ii1] = fy0;
                sY[tauB*17 + ii1] = fy1;
            }
        }
        __syncthreads();

        // ---- U[tau][ii] = Ti[tau,:] . G[ii,:]  (both contiguous) ----
        {
            float4 t0 = *(const float4*)&S.Ti[tauU][0];
            float4 t1 = *(const float4*)&S.Ti[tauU][4];
            float4 t2 = *(const float4*)&S.Ti[tauU][8];
            float4 t3 = *(const float4*)&S.Ti[tauU][12];
            const float4* g4 = (const float4*)&sGt[iiU*20];
            float4 G0 = g4[0], G1 = g4[1], G2 = g4[2], G3 = g4[3];
            float u;
            u = t0.x * G0.x;
            u = fmaf(t0.y, G0.y, u); u = fmaf(t0.z, G0.z, u); u = fmaf(t0.w, G0.w, u);
            u = fmaf(t1.x, G1.x, u); u = fmaf(t1.y, G1.y, u);
            u = fmaf(t1.z, G1.z, u); u = fmaf(t1.w, G1.w, u);
            u = fmaf(t2.x, G2.x, u); u = fmaf(t2.y, G2.y, u);
            u = fmaf(t2.z, G2.z, u); u = fmaf(t2.w, G2.w, u);
            u = fmaf(t3.x, G3.x, u); u = fmaf(t3.y, G3.y, u);
            u = fmaf(t3.z, G3.z, u); u = fmaf(t3.w, G3.w, u);
            if (lane < 16) sUt[iiU*20 + tauU] = u;
        }
        __syncthreads();

        // ---- Y finalize: y = Y0 + RKV + RB[tau,:].U[ii,:]; store ----
        {
            float yv = sY[tauU*17 + iiU] + S.RKV[tauU][iiU];
            float4 b0 = *(const float4*)&S.RBm[tauU][0];
            float4 b1 = *(const float4*)&S.RBm[tauU][4];
            float4 b2 = *(const float4*)&S.RBm[tauU][8];
            float4 b3 = *(const float4*)&S.RBm[tauU][12];
            const float4* u4 = (const float4*)&sUt[iiU*20];
            float4 U0 = u4[0], U1 = u4[1], U2 = u4[2], U3 = u4[3];
            yv = fmaf(b0.x, U0.x, yv); yv = fmaf(b0.y, U0.y, yv);
            yv = fmaf(b0.z, U0.z, yv); yv = fmaf(b0.w, U0.w, yv);
            yv = fmaf(b1.x, U1.x, yv); yv = fmaf(b1.y, U1.y, yv);
            yv = fmaf(b1.z, U1.z, yv); yv = fmaf(b1.w, U1.w, yv);
            yv = fmaf(b2.x, U2.x, yv); yv = fmaf(b2.y, U2.y, yv);
            yv = fmaf(b2.z, U2.z, yv); yv = fmaf(b2.w, U2.w, yv);
            yv = fmaf(b3.x, U3.x, yv); yv = fmaf(b3.y, U3.y, yv);
            yv = fmaf(b3.z, U3.z, yv); yv = fmaf(b3.w, U3.w, yv);
            if (lane < 16)
                yOut[((size_t)(c*L + tauU) * HH + h) * NN + i0 + iiU] = yv;
        }

        // ---- S update: S[iiS][jb..jb+1] = wL.S + B^T U + K^T V ----
        {
            float uu[16], vv[16];
            const float4* up = (const float4*)&sUt[iiS*20];
            const float4* vp = (const float4*)&S.Vt[iiS][0];
            ((float4*)uu)[0] = up[0]; ((float4*)uu)[1] = up[1];
            ((float4*)uu)[2] = up[2]; ((float4*)uu)[3] = up[3];
            ((float4*)vv)[0] = vp[0]; ((float4*)vv)[1] = vp[1];
            ((float4*)vv)[2] = vp[2]; ((float4*)vv)[3] = vp[3];

            u64* srow = (u64*)&sS[iiS*68 + jb];
            const u64 wl = *(const u64*)&S.wL[jb];
            u64 n = mul2(srow[0], wl);
            #pragma unroll
            for (int s = 0; s < L; ++s) {
                u64 bv = *(const u64*)&S.Bq[s][jb];
                u64 kv = *(const u64*)&S.Kq[s][jb];
                n = fma2(bv, bcast2(uu[s]), n);
                n = fma2(kv, bcast2(vv[s]), n);
            }
            srow[0] = n;
        }
    }

    // ---- final state ----
    __syncthreads();
    #pragma unroll
    for (int r = 0; r < 2; ++r) {
        int idx = tid + r*512;
        int si = idx >> 6, j = idx & 63;
        sOut[((size_t)h*NN + i0 + si)*NN + j] = sS[si*68 + j];
    }
}

extern "C" void kernel_launch(void* const* d_in, const int* in_sizes, int n_in,
                              void* d_out, int out_size)
{
    const float* r  = (const float*)d_in[0];
    const float* w  = (const float*)d_in[1];
    const float* k  = (const float*)d_in[2];
    const float* v  = (const float*)d_in[3];
    const float* a  = (const float*)d_in[4];
    const float* b  = (const float*)d_in[5];
    const float* st = (const float*)d_in[6];

    const int T  = in_sizes[0] / (HH * NN);
    const int NC = T / L;

    float* y    = (float*)d_out;
    float* sfin = y + (size_t)T * HH * NN;

    const int smem2 = (3*STAGE_F + 16*68 + 2*16*20 + 16*17) * 4;
    cudaFuncSetAttribute(wkv7_k2, cudaFuncAttributeMaxDynamicSharedMemorySize, smem2);

    wkv7_k1<<<NC * HH, 128>>>(r, w, k, v, a, b);
    wkv7_k2<<<HH * 4, 512, smem2>>>(st, y, sfin, NC);
}

// round 13
// speedup vs baseline: 1.2609x; 1.2609x over previous
#include <cuda_runtime.h>
#include <cstdint>

// RWKV7 WKV — chunked UT-transform, L=16 (v6 = R11 + transposed G/U/V reads).
// k1: per (chunk,head) precompute (parallel, 8192 CTAs).
// k2: serial over chunks, 128 CTAs x 256 threads; R11 warp mappings;
//     G,U stored [ii][20] and V [ii][s] so all small-matrix consumption is
//     float4-contiguous (kills the scalar column-strided LDS streams).

#define HH 32
#define NN 64
#define L  16
#define NCMAX 256

typedef unsigned long long u64;

__device__ float g_At [NCMAX*HH*L*NN];
__device__ float g_Rt [NCMAX*HH*L*NN];
__device__ float g_Bh [NCMAX*HH*L*NN];
__device__ float g_Kh [NCMAX*HH*L*NN];
__device__ float g_MV [NCMAX*HH*L*NN];
__device__ float g_RKV[NCMAX*HH*L*NN];
__device__ float g_Vt [NCMAX*HH*NN*L];   // [c][h][i][s]
__device__ float g_Ti [NCMAX*HH*L*L];
__device__ float g_RB [NCMAX*HH*L*L];
__device__ float g_wL [NCMAX*HH*NN];

__device__ __forceinline__ u64 fma2(u64 a, u64 b, u64 c) {
    u64 d; asm("fma.rn.f32x2 %0, %1, %2, %3;" : "=l"(d) : "l"(a), "l"(b), "l"(c)); return d;
}
__device__ __forceinline__ u64 add2(u64 a, u64 b) {
    u64 d; asm("add.rn.f32x2 %0, %1, %2;" : "=l"(d) : "l"(a), "l"(b)); return d;
}
__device__ __forceinline__ u64 mul2(u64 a, u64 b) {
    u64 d; asm("mul.rn.f32x2 %0, %1, %2;" : "=l"(d) : "l"(a), "l"(b)); return d;
}
__device__ __forceinline__ u64 bcast2(float x) {
    u64 d; asm("mov.b64 %0, {%1, %1};" : "=l"(d) : "f"(x)); return d;
}
__device__ __forceinline__ float hsum2(u64 a) {
    float x, y; asm("mov.b64 {%0, %1}, %2;" : "=f"(x), "=f"(y) : "l"(a)); return x + y;
}
__device__ __forceinline__ void cp_async16(void* smem_dst, const void* gsrc) {
    unsigned saddr = (unsigned)__cvta_generic_to_shared(smem_dst);
    asm volatile("cp.async.ca.shared.global [%0], [%1], 16;\n"
                 :: "r"(saddr), "l"(gsrc) : "memory");
}

// ================= kernel 1: per-chunk precompute (parallel) ===============
__global__ __launch_bounds__(128)
void wkv7_k1(const float* __restrict__ rP, const float* __restrict__ wP,
             const float* __restrict__ kP, const float* __restrict__ vP,
             const float* __restrict__ aP, const float* __restrict__ bP)
{
    const int c = blockIdx.x >> 5, h = blockIdx.x & 31, tid = threadIdx.x;

    __shared__ float sW[L][68], sA[L][68], sB[L][68], sK[L][68], sR[L][68], sV[L][68];
    __shared__ float sC[L][17], sM[L][17], sRBm[L][17], sRKm[L][17], sTi[L][17];

    for (int idx = tid; idx < L*NN; idx += 128) {
        int tau = idx >> 6, j = idx & 63;
        size_t g = ((size_t)(c*L + tau) * HH + h) * NN + j;
        sW[tau][j] = fmaxf(wP[g], 1e-9f);
        sA[tau][j] = aP[g]; sB[tau][j] = bP[g]; sK[tau][j] = kP[g];
        sR[tau][j] = rP[g]; sV[tau][j] = vP[g];
    }
    __syncthreads();

    if (tid < NN) {
        float run = 1.f;
        #pragma unroll
        for (int tau = 0; tau < L; ++tau) { run *= sW[tau][tid]; sW[tau][tid] = run; }
    }
    __syncthreads();

    for (int idx = tid; idx < L*NN; idx += 128) {
        int tau = idx >> 6, j = idx & 63;
        float Wc = sW[tau][j];
        float Wp = tau ? sW[tau-1][j] : 1.f;
        float inv = 1.f / Wc;
        sA[tau][j] *= Wp; sB[tau][j] *= inv; sK[tau][j] *= inv; sR[tau][j] *= Wc;
    }
    __syncthreads();

    {
        const int s = tid & 15;
        const int tau1 = tid >> 4, tau2 = tau1 + 8;
        const u64* Bp = (const u64*)&sB[s][0];
        const u64* Kp = (const u64*)&sK[s][0];
        const u64* A1 = (const u64*)&sA[tau1][0];
        const u64* R1 = (const u64*)&sR[tau1][0];
        const u64* A2 = (const u64*)&sA[tau2][0];
        const u64* R2 = (const u64*)&sR[tau2][0];
        u64 c1=0,m1=0,rb1=0,rk1=0, c2=0,m2=0,rb2=0,rk2=0;
        #pragma unroll 8
        for (int p = 0; p < 32; ++p) {
            u64 bs = Bp[p], ks = Kp[p];
            u64 a1 = A1[p], r1 = R1[p], a2 = A2[p], r2 = R2[p];
            c1 = fma2(a1, bs, c1);  m1 = fma2(a1, ks, m1);
            rb1 = fma2(r1, bs, rb1); rk1 = fma2(r1, ks, rk1);
            c2 = fma2(a2, bs, c2);  m2 = fma2(a2, ks, m2);
            rb2 = fma2(r2, bs, rb2); rk2 = fma2(r2, ks, rk2);
        }
        float fc1=hsum2(c1), fm1=hsum2(m1), frb1=hsum2(rb1), frk1=hsum2(rk1);
        float fc2=hsum2(c2), fm2=hsum2(m2), frb2=hsum2(rb2), frk2=hsum2(rk2);
        if (s >  tau1) { frb1 = 0.f; frk1 = 0.f; }
        if (s >= tau1) { fc1 = 0.f;  fm1 = 0.f; }
        if (s >  tau2) { frb2 = 0.f; frk2 = 0.f; }
        if (s >= tau2) { fc2 = 0.f;  fm2 = 0.f; }
        sC[tau1][s]=fc1; sM[tau1][s]=fm1; sRBm[tau1][s]=frb1; sRKm[tau1][s]=frk1;
        sC[tau2][s]=fc2; sM[tau2][s]=fm2; sRBm[tau2][s]=frb2; sRKm[tau2][s]=frk2;
    }
    __syncthreads();

    if (tid < L) {
        const int s = tid;
        for (int tau = 0; tau < L; ++tau) {
            float x = (tau == s) ? 1.f : 0.f;
            for (int u = s; u < tau; ++u) x = fmaf(sC[tau][u], sTi[u][s], x);
            sTi[tau][s] = (tau >= s) ? x : 0.f;
        }
    }
    __syncthreads();

    const size_t LN = ((size_t)c*HH + h) * (L*NN);

    #pragma unroll
    for (int g2 = 0; g2 < 2; ++g2) {
        int grp = tid + g2*128;
        int tau = grp >> 4, i4 = (grp & 15) * 4;
        u64 mv0=0, mv1=0, rk0=0, rk1=0;
        #pragma unroll
        for (int s = 0; s < L; ++s) {
            const u64* vp = (const u64*)&sV[s][i4];
            u64 v0 = vp[0], v1 = vp[1];
            u64 m2b = bcast2(sM[tau][s]);
            u64 k2b = bcast2(sRKm[tau][s]);
            mv0 = fma2(m2b, v0, mv0); mv1 = fma2(m2b, v1, mv1);
            rk0 = fma2(k2b, v0, rk0); rk1 = fma2(k2b, v1, rk1);
        }
        u64* od = (u64*)(g_MV + LN + tau*NN + i4);
        od[0] = mv0; od[1] = mv1;
        u64* od2 = (u64*)(g_RKV + LN + tau*NN + i4);
        od2[0] = rk0; od2[1] = rk1;
    }

    for (int idx = tid; idx < L*NN; idx += 128) {
        int tau = idx >> 6, j = idx & 63;
        float wl = sW[L-1][j];
        g_At[LN+idx] = sA[tau][j];
        g_Rt[LN+idx] = sR[tau][j];
        g_Bh[LN+idx] = sB[tau][j] * wl;
        g_Kh[LN+idx] = sK[tau][j] * wl;
    }
    // transposed V: [i][s]
    const size_t VT = ((size_t)c*HH + h) * (NN*L);
    for (int idx = tid; idx < NN*L; idx += 128) {
        int i = idx >> 4, s = idx & 15;
        g_Vt[VT + idx] = sV[s][i];
    }
    const size_t Tb = ((size_t)c*HH + h) * (L*L);
    for (int idx = tid; idx < 256; idx += 128) {
        g_Ti[Tb+idx] = sTi[idx>>4][idx&15];
        g_RB[Tb+idx] = sRBm[idx>>4][idx&15];
    }
    if (tid < NN) g_wL[((size_t)c*HH + h)*NN + tid] = sW[L-1][tid];
}

// ================= kernel 2: serial over chunks (256 threads) ==============
struct Stage {
    float Aq[L][68], Rq[L][68], Bq[L][68], Kq[L][68];
    float Ti[L][20], RBm[L][20];
    float MV[L][16], RKV[L][16];
    float Vt[16][16];        // [ii][s]
    float wL[64];
};
#define STAGE_F ((int)(sizeof(Stage)/4))

__device__ __forceinline__ void loadStage(Stage& st, int c, int h, int i0, int tid)
{
    const size_t LN = ((size_t)c*HH + h) * (L*NN);
    const size_t Tb = ((size_t)c*HH + h) * (L*L);
    const size_t VT = ((size_t)c*HH + h) * (NN*L);
    {
        int row = tid >> 4, q = (tid & 15) * 4;
        cp_async16(&st.Aq[row][q], g_At + LN + row*NN + q);
        cp_async16(&st.Rq[row][q], g_Rt + LN + row*NN + q);
        cp_async16(&st.Bq[row][q], g_Bh + LN + row*NN + q);
        cp_async16(&st.Kq[row][q], g_Kh + LN + row*NN + q);
    }
    if (tid < 128) {
        int sel = tid >> 6, e = tid & 63, row = e >> 2, q = (e & 3) * 4;
        if (sel == 0) cp_async16(&st.Ti [row][q], g_Ti + Tb + row*L + q);
        else          cp_async16(&st.RBm[row][q], g_RB + Tb + row*L + q);
    }
    if (tid < 192) {
        int sel = tid >> 6, e = tid & 63, row = e >> 2, q = (e & 3) * 4;
        if (sel == 0)      cp_async16(&st.MV [row][q], g_MV  + LN + row*NN + i0 + q);
        else if (sel == 1) cp_async16(&st.RKV[row][q], g_RKV + LN + row*NN + i0 + q);
        else               cp_async16(&st.Vt [row][q],
                               g_Vt + VT + (size_t)(i0 + row)*L + q);
    }
    if (tid < 16) cp_async16(&st.wL[tid*4], g_wL + ((size_t)c*HH + h)*NN + tid*4);
}

__global__ __launch_bounds__(256, 1)
void wkv7_k2(const float* __restrict__ stateP,
             float* __restrict__ yOut, float* __restrict__ sOut, int NC)
{
    extern __shared__ float dyn[];
    Stage* st  = (Stage*)dyn;
    float* sS  = dyn + 3*STAGE_F;        // [16][68]
    float* sGt = sS + 16*68;             // [16][20]  (ii, tau)
    float* sUt = sGt + 16*20;            // [16][20]  (ii, tau)
    float* sY  = sUt + 16*20;            // [16][17]  (tau, ii)

    const int tid = threadIdx.x;
    const int h  = blockIdx.x >> 2, sl = blockIdx.x & 3;
    const int i0 = sl * 16;

    const int warp = tid >> 5, lane = tid & 31;
    // stage 1 (G/Y dots): warp owns taus {2w,2w+1}; lanes = (ii:16, jh:2)
    const int ii1 = lane & 15, jh = lane >> 4;
    const int tauA = warp*2, tauB = warp*2 + 1;
    // stage U / Yfin: lanes = (ii:16, tt:2); tau = 2w + tt — all lanes active
    const int tt   = lane >> 4;
    const int tauU = warp*2 + tt;
    // S-update: warp owns j-slice [8w, 8w+8); lanes = (ii:16, jq:2)
    const int jb  = warp*8 + (lane >> 4)*4;

    // ---- state into SMEM ----
    #pragma unroll
    for (int r = 0; r < 4; ++r) {
        int idx = tid + r*256;
        int si = idx >> 6, j = idx & 63;
        sS[si*68 + j] = stateP[((size_t)h*NN + i0 + si)*NN + j];
    }

    if (NC > 0) loadStage(st[0], 0, h, i0, tid);
    asm volatile("cp.async.commit_group;\n" ::: "memory");
    if (NC > 1) loadStage(st[1], 1, h, i0, tid);
    asm volatile("cp.async.commit_group;\n" ::: "memory");

    #pragma unroll 1
    for (int c = 0; c < NC; ++c) {
        asm volatile("cp.async.wait_group 1;\n" ::: "memory");
        __syncthreads();
        if (c + 2 < NC) loadStage(st[(c+2)%3], c+2, h, i0, tid);
        asm volatile("cp.async.commit_group;\n" ::: "memory");

        Stage& S = st[c % 3];

        // ---- stage 1: G[tau][ii] = A~[tau].S[ii], Y0 = R~[tau].S[ii] ----
        {
            const float* Ar0 = &S.Aq[tauA][jh*4];
            const float* Ar1 = &S.Aq[tauB][jh*4];
            const float* Rr0 = &S.Rq[tauA][jh*4];
            const float* Rr1 = &S.Rq[tauB][jh*4];
            const float* Srw = &sS[ii1*68 + jh*4];
            u64 g0=0, g1=0, q0=0, q1=0;
            #pragma unroll
            for (int p = 0; p < 8; ++p) {
                ulonglong2 sv = *(const ulonglong2*)(Srw + p*8);
                ulonglong2 a0 = *(const ulonglong2*)(Ar0 + p*8);
                ulonglong2 a1 = *(const ulonglong2*)(Ar1 + p*8);
                ulonglong2 r0 = *(const ulonglong2*)(Rr0 + p*8);
                ulonglong2 r1 = *(const ulonglong2*)(Rr1 + p*8);
                g0 = fma2(a0.x, sv.x, g0); g0 = fma2(a0.y, sv.y, g0);
                g1 = fma2(a1.x, sv.x, g1); g1 = fma2(a1.y, sv.y, g1);
                q0 = fma2(r0.x, sv.x, q0); q0 = fma2(r0.y, sv.y, q0);
                q1 = fma2(r1.x, sv.x, q1); q1 = fma2(r1.y, sv.y, q1);
            }
            float fg0 = hsum2(g0), fg1 = hsum2(g1);
            float fy0 = hsum2(q0), fy1 = hsum2(q1);
            fg0 += __shfl_xor_sync(0xffffffffu, fg0, 16);
            fg1 += __shfl_xor_sync(0xffffffffu, fg1, 16);
            fy0 += __shfl_xor_sync(0xffffffffu, fy0, 16);
            fy1 += __shfl_xor_sync(0xffffffffu, fy1, 16);
            if (jh == 0) {
                sGt[ii1*20 + tauA] = fg0 + S.MV[tauA][ii1];
                sGt[ii1*20 + tauB] = fg1 + S.MV[tauB][ii1];
                sY[tauA*17 + ii1] = fy0;
                sY[tauB*17 + ii1] = fy1;
            }
        }
        __syncthreads();

        // ---- U[tau][ii] = Ti[tau,:] . G[ii,:] (all float4 reads) ----
        {
            float4 t0 = *(const float4*)&S.Ti[tauU][0];
            float4 t1 = *(const float4*)&S.Ti[tauU][4];
            float4 t2 = *(const float4*)&S.Ti[tauU][8];
            float4 t3 = *(const float4*)&S.Ti[tauU][12];
            const float4* g4 = (const float4*)&sGt[ii1*20];
            float4 G0 = g4[0], G1 = g4[1], G2 = g4[2], G3 = g4[3];
            float u;
            u = t0.x * G0.x;
            u = fmaf(t0.y, G0.y, u); u = fmaf(t0.z, G0.z, u); u = fmaf(t0.w, G0.w, u);
            u = fmaf(t1.x, G1.x, u); u = fmaf(t1.y, G1.y, u);
            u = fmaf(t1.z, G1.z, u); u = fmaf(t1.w, G1.w, u);
            u = fmaf(t2.x, G2.x, u); u = fmaf(t2.y, G2.y, u);
            u = fmaf(t2.z, G2.z, u); u = fmaf(t2.w, G2.w, u);
            u = fmaf(t3.x, G3.x, u); u = fmaf(t3.y, G3.y, u);
            u = fmaf(t3.z, G3.z, u); u = fmaf(t3.w, G3.w, u);
            sUt[ii1*20 + tauU] = u;
        }
        __syncthreads();

        // ---- Y finalize: y = Y0 + RKV + RB[tau,:].U[ii,:]; store ----
        {
            float yv = sY[tauU*17 + ii1] + S.RKV[tauU][ii1];
            float4 b0 = *(const float4*)&S.RBm[tauU][0];
            float4 b1 = *(const float4*)&S.RBm[tauU][4];
            float4 b2 = *(const float4*)&S.RBm[tauU][8];
            float4 b3 = *(const float4*)&S.RBm[tauU][12];
            const float4* u4 = (const float4*)&sUt[ii1*20];
            float4 U0 = u4[0], U1 = u4[1], U2 = u4[2], U3 = u4[3];
            yv = fmaf(b0.x, U0.x, yv); yv = fmaf(b0.y, U0.y, yv);
            yv = fmaf(b0.z, U0.z, yv); yv = fmaf(b0.w, U0.w, yv);
            yv = fmaf(b1.x, U1.x, yv); yv = fmaf(b1.y, U1.y, yv);
            yv = fmaf(b1.z, U1.z, yv); yv = fmaf(b1.w, U1.w, yv);
            yv = fmaf(b2.x, U2.x, yv); yv = fmaf(b2.y, U2.y, yv);
            yv = fmaf(b2.z, U2.z, yv); yv = fmaf(b2.w, U2.w, yv);
            yv = fmaf(b3.x, U3.x, yv); yv = fmaf(b3.y, U3.y, yv);
            yv = fmaf(b3.z, U3.z, yv); yv = fmaf(b3.w, U3.w, yv);
            yOut[((size_t)(c*L + tauU) * HH + h) * NN + i0 + ii1] = yv;
        }

        // ---- S update: warp's j-slice. S = wL.S + B^T U + K^T V ----
        {
            float uu[16], vv[16];
            {
                const float4* up = (const float4*)&sUt[ii1*20];
                const float4* vp = (const float4*)&S.Vt[ii1][0];
                ((float4*)uu)[0] = up[0]; ((float4*)uu)[1] = up[1];
                ((float4*)uu)[2] = up[2]; ((float4*)uu)[3] = up[3];
                ((float4*)vv)[0] = vp[0]; ((float4*)vv)[1] = vp[1];
                ((float4*)vv)[2] = vp[2]; ((float4*)vv)[3] = vp[3];
            }
            u64* srow = (u64*)&sS[ii1*68 + jb];
            const u64* wl = (const u64*)&S.wL[jb];
            u64 n0 = mul2(srow[0], wl[0]);
            u64 n1 = mul2(srow[1], wl[1]);
            #pragma unroll
            for (int s = 0; s < L; ++s) {
                u64 u2 = bcast2(uu[s]);
                u64 v2 = bcast2(vv[s]);
                ulonglong2 bv = *(const ulonglong2*)&S.Bq[s][jb];
                ulonglong2 kv = *(const ulonglong2*)&S.Kq[s][jb];
                n0 = fma2(bv.x, u2, n0); n0 = fma2(kv.x, v2, n0);
                n1 = fma2(bv.y, u2, n1); n1 = fma2(kv.y, v2, n1);
            }
            srow[0] = n0; srow[1] = n1;
        }
    }

    // ---- final state ----
    __syncthreads();
    #pragma unroll
    for (int r = 0; r < 4; ++r) {
        int idx = tid + r*256;
        int si = idx >> 6, j = idx & 63;
        sOut[((size_t)h*NN + i0 + si)*NN + j] = sS[si*68 + j];
    }
}

extern "C" void kernel_launch(void* const* d_in, const int* in_sizes, int n_in,
                              void* d_out, int out_size)
{
    const float* r  = (const float*)d_in[0];
    const float* w  = (const float*)d_in[1];
    const float* k  = (const float*)d_in[2];
    const float* v  = (const float*)d_in[3];
    const float* a  = (const float*)d_in[4];
    const float* b  = (const float*)d_in[5];
    const float* st = (const float*)d_in[6];

    const int T  = in_sizes[0] / (HH * NN);
    const int NC = T / L;

    float* y    = (float*)d_out;
    float* sfin = y + (size_t)T * HH * NN;

    const int smem2 = (3*STAGE_F + 16*68 + 2*16*20 + 16*17) * 4;
    cudaFuncSetAttribute(wkv7_k2, cudaFuncAttributeMaxDynamicSharedMemorySize, smem2);

    wkv7_k1<<<NC * HH, 128>>>(r, w, k, v, a, b);
    wkv7_k2<<<HH * 4, 256, smem2>>>(st, y, sfin, NC);
}

// round 14
// speedup vs baseline: 1.4803x; 1.1740x over previous
#include <cuda_runtime.h>
#include <cstdint>

// RWKV7 WKV — chunked UT-transform, L=16 (v7 = R11 k2 verbatim + fast k1).
// k1: per (chunk,head) precompute, 256 threads, register-resident
//     cumprod/Tinv chains (latency cut ~2x).
// k2: serial over chunks, 128 CTAs x 256 threads (exact R11 code, 348.8us).

#define HH 32
#define NN 64
#define L  16
#define NCMAX 256

typedef unsigned long long u64;

__device__ float g_At [NCMAX*HH*L*NN];
__device__ float g_Rt [NCMAX*HH*L*NN];
__device__ float g_Bh [NCMAX*HH*L*NN];
__device__ float g_Kh [NCMAX*HH*L*NN];
__device__ float g_MV [NCMAX*HH*L*NN];
__device__ float g_RKV[NCMAX*HH*L*NN];
__device__ float g_Ti [NCMAX*HH*L*L];
__device__ float g_RB [NCMAX*HH*L*L];
__device__ float g_wL [NCMAX*HH*NN];

__device__ __forceinline__ u64 fma2(u64 a, u64 b, u64 c) {
    u64 d; asm("fma.rn.f32x2 %0, %1, %2, %3;" : "=l"(d) : "l"(a), "l"(b), "l"(c)); return d;
}
__device__ __forceinline__ u64 add2(u64 a, u64 b) {
    u64 d; asm("add.rn.f32x2 %0, %1, %2;" : "=l"(d) : "l"(a), "l"(b)); return d;
}
__device__ __forceinline__ u64 mul2(u64 a, u64 b) {
    u64 d; asm("mul.rn.f32x2 %0, %1, %2;" : "=l"(d) : "l"(a), "l"(b)); return d;
}
__device__ __forceinline__ u64 bcast2(float x) {
    u64 d; asm("mov.b64 %0, {%1, %1};" : "=l"(d) : "f"(x)); return d;
}
__device__ __forceinline__ float hsum2(u64 a) {
    float x, y; asm("mov.b64 {%0, %1}, %2;" : "=f"(x), "=f"(y) : "l"(a)); return x + y;
}
__device__ __forceinline__ void cp_async16(void* smem_dst, const void* gsrc) {
    unsigned saddr = (unsigned)__cvta_generic_to_shared(smem_dst);
    asm volatile("cp.async.ca.shared.global [%0], [%1], 16;\n"
                 :: "r"(saddr), "l"(gsrc) : "memory");
}

// ================= kernel 1: per-chunk precompute (parallel, 256 thr) ======
__global__ __launch_bounds__(256)
void wkv7_k1(const float* __restrict__ rP, const float* __restrict__ wP,
             const float* __restrict__ kP, const float* __restrict__ vP,
             const float* __restrict__ aP, const float* __restrict__ bP)
{
    const int c = blockIdx.x >> 5, h = blockIdx.x & 31, tid = threadIdx.x;

    __shared__ float sW[L][68], sA[L][68], sB[L][68], sK[L][68], sR[L][68], sV[L][68];
    __shared__ float sC[L][17], sM[L][17], sRBm[L][17], sRKm[L][17], sTi[L][17];

    #pragma unroll
    for (int r = 0; r < 4; ++r) {
        int idx = tid + r*256;
        int tau = idx >> 6, j = idx & 63;
        size_t g = ((size_t)(c*L + tau) * HH + h) * NN + j;
        sW[tau][j] = fmaxf(wP[g], 1e-9f);
        sA[tau][j] = aP[g]; sB[tau][j] = bP[g]; sK[tau][j] = kP[g];
        sR[tau][j] = rP[g]; sV[tau][j] = vP[g];
    }
    __syncthreads();

    // cumprod per key column — batch loads, register chain, single store pass
    if (tid < NN) {
        float wv[L];
        #pragma unroll
        for (int tau = 0; tau < L; ++tau) wv[tau] = sW[tau][tid];
        float run = 1.f;
        #pragma unroll
        for (int tau = 0; tau < L; ++tau) { run *= wv[tau]; sW[tau][tid] = run; }
    }
    __syncthreads();

    #pragma unroll
    for (int r = 0; r < 4; ++r) {
        int idx = tid + r*256;
        int tau = idx >> 6, j = idx & 63;
        float Wc = sW[tau][j];
        float Wp = tau ? sW[tau-1][j] : 1.f;
        float inv = 1.f / Wc;
        sA[tau][j] *= Wp; sB[tau][j] *= inv; sK[tau][j] *= inv; sR[tau][j] *= Wc;
    }
    __syncthreads();

    // triangular coefficient matrices — one (tau,s) pair per thread
    {
        const int s = tid & 15, tau = tid >> 4;
        const u64* Bp = (const u64*)&sB[s][0];
        const u64* Kp = (const u64*)&sK[s][0];
        const u64* Ap = (const u64*)&sA[tau][0];
        const u64* Rp = (const u64*)&sR[tau][0];
        u64 c1=0, m1=0, rb1=0, rk1=0;
        #pragma unroll 8
        for (int p = 0; p < 32; ++p) {
            u64 bs = Bp[p], ks = Kp[p], a1 = Ap[p], r1 = Rp[p];
            c1 = fma2(a1, bs, c1);   m1 = fma2(a1, ks, m1);
            rb1 = fma2(r1, bs, rb1); rk1 = fma2(r1, ks, rk1);
        }
        float fc=hsum2(c1), fm=hsum2(m1), frb=hsum2(rb1), frk=hsum2(rk1);
        if (s >  tau) { frb = 0.f; frk = 0.f; }
        if (s >= tau) { fc = 0.f;  fm = 0.f; }
        sC[tau][s]=fc; sM[tau][s]=fm; sRBm[tau][s]=frb; sRKm[tau][s]=frk;
    }
    __syncthreads();

    // Tinv = (I - C)^{-1}, unit lower triangular; register-resident column
    if (tid < L) {
        const int s = tid;
        float col[L];
        #pragma unroll
        for (int tau = 0; tau < L; ++tau) {
            float x = (tau == s) ? 1.f : 0.f;
            #pragma unroll
            for (int u = 0; u < L; ++u)
                if (u < tau) x = fmaf(sC[tau][u], col[u], x);
            col[tau] = x;   // zeros propagate naturally for tau < s
        }
        #pragma unroll
        for (int tau = 0; tau < L; ++tau) sTi[tau][s] = col[tau];
    }
    __syncthreads();

    const size_t LN = ((size_t)c*HH + h) * (L*NN);

    // MV = M V, RKV = RK V — one (tau, i4) group per thread
    {
        const int tau = tid >> 4, i4 = (tid & 15) * 4;
        u64 mv0=0, mv1=0, rk0=0, rk1=0;
        #pragma unroll
        for (int s = 0; s < L; ++s) {
            const u64* vp = (const u64*)&sV[s][i4];
            u64 v0 = vp[0], v1 = vp[1];
            u64 m2b = bcast2(sM[tau][s]);
            u64 k2b = bcast2(sRKm[tau][s]);
            mv0 = fma2(m2b, v0, mv0); mv1 = fma2(m2b, v1, mv1);
            rk0 = fma2(k2b, v0, rk0); rk1 = fma2(k2b, v1, rk1);
        }
        u64* od = (u64*)(g_MV + LN + tau*NN + i4);
        od[0] = mv0; od[1] = mv1;
        u64* od2 = (u64*)(g_RKV + LN + tau*NN + i4);
        od2[0] = rk0; od2[1] = rk1;
    }

    // export a~, r~, b^, k^
    #pragma unroll
    for (int r = 0; r < 4; ++r) {
        int idx = tid + r*256;
        int tau = idx >> 6, j = idx & 63;
        float wl = sW[L-1][j];
        g_At[LN+idx] = sA[tau][j];
        g_Rt[LN+idx] = sR[tau][j];
        g_Bh[LN+idx] = sB[tau][j] * wl;
        g_Kh[LN+idx] = sK[tau][j] * wl;
    }
    const size_t Tb = ((size_t)c*HH + h) * (L*L);
    if (tid < 256) {
        g_Ti[Tb+tid] = sTi[tid>>4][tid&15];
        g_RB[Tb+tid] = sRBm[tid>>4][tid&15];
    }
    if (tid < NN) g_wL[((size_t)c*HH + h)*NN + tid] = sW[L-1][tid];
}

// ================= kernel 2: serial over chunks (exact R11) =================
struct Stage {
    float Aq[L][68], Rq[L][68], Bq[L][68], Kq[L][68];
    float Ti[L][20], RBm[L][20];
    float MV[L][16], RKV[L][16], V[L][16];
    float wL[64];
};
#define STAGE_F ((int)(sizeof(Stage)/4))

__device__ __forceinline__ void loadStage(Stage& st, int c, int h, int i0, int tid,
                                          const float* __restrict__ vP)
{
    const size_t LN = ((size_t)c*HH + h) * (L*NN);
    const size_t Tb = ((size_t)c*HH + h) * (L*L);
    {
        int row = tid >> 4, q = (tid & 15) * 4;
        cp_async16(&st.Aq[row][q], g_At + LN + row*NN + q);
        cp_async16(&st.Rq[row][q], g_Rt + LN + row*NN + q);
        cp_async16(&st.Bq[row][q], g_Bh + LN + row*NN + q);
        cp_async16(&st.Kq[row][q], g_Kh + LN + row*NN + q);
    }
    if (tid < 128) {
        int sel = tid >> 6, e = tid & 63, row = e >> 2, q = (e & 3) * 4;
        if (sel == 0) cp_async16(&st.Ti [row][q], g_Ti + Tb + row*L + q);
        else          cp_async16(&st.RBm[row][q], g_RB + Tb + row*L + q);
    }
    if (tid < 192) {
        int sel = tid >> 6, e = tid & 63, row = e >> 2, q = (e & 3) * 4;
        if (sel == 0)      cp_async16(&st.MV [row][q], g_MV  + LN + row*NN + i0 + q);
        else if (sel == 1) cp_async16(&st.RKV[row][q], g_RKV + LN + row*NN + i0 + q);
        else               cp_async16(&st.V  [row][q],
                               vP + ((size_t)(c*L + row)*HH + h)*NN + i0 + q);
    }
    if (tid < 16) cp_async16(&st.wL[tid*4], g_wL + ((size_t)c*HH + h)*NN + tid*4);
}

__global__ __launch_bounds__(256, 1)
void wkv7_k2(const float* __restrict__ vP, const float* __restrict__ stateP,
             float* __restrict__ yOut, float* __restrict__ sOut, int NC)
{
    extern __shared__ float dyn[];
    Stage* st = (Stage*)dyn;
    float* sS = dyn + 3*STAGE_F;            // [16][68]
    float* sG = sS + 16*68;                 // [16][17]
    float* sU = sG + 16*17;                 // [16][17]
    float* sY = sU + 16*17;                 // [16][17]

    const int tid = threadIdx.x;
    const int h  = blockIdx.x >> 2, sl = blockIdx.x & 3;
    const int i0 = sl * 16;

    const int warp = tid >> 5, lane = tid & 31;
    const int ii1 = lane & 15, jh = lane >> 4;
    const int tauA = warp*2, tauB = warp*2 + 1;
    const int tauU = warp*2 + (lane >> 4);
    const int jb = warp*8 + (lane >> 4)*4;

    #pragma unroll
    for (int r = 0; r < 4; ++r) {
        int idx = tid + r*256;
        int si = idx >> 6, j = idx & 63;
        sS[si*68 + j] = stateP[((size_t)h*NN + i0 + si)*NN + j];
    }

    if (NC > 0) loadStage(st[0], 0, h, i0, tid, vP);
    asm volatile("cp.async.commit_group;\n" ::: "memory");
    if (NC > 1) loadStage(st[1], 1, h, i0, tid, vP);
    asm volatile("cp.async.commit_group;\n" ::: "memory");

    #pragma unroll 1
    for (int c = 0; c < NC; ++c) {
        asm volatile("cp.async.wait_group 1;\n" ::: "memory");
        __syncthreads();
        if (c + 2 < NC) loadStage(st[(c+2)%3], c+2, h, i0, tid, vP);
        asm volatile("cp.async.commit_group;\n" ::: "memory");

        Stage& S = st[c % 3];

        // ---- stage 1: G[tau][ii] = A~[tau].S[ii], Y0 = R~[tau].S[ii] ----
        {
            const float* Ar0 = &S.Aq[tauA][jh*4];
            const float* Ar1 = &S.Aq[tauB][jh*4];
            const float* Rr0 = &S.Rq[tauA][jh*4];
            const float* Rr1 = &S.Rq[tauB][jh*4];
            const float* Srw = &sS[ii1*68 + jh*4];
            u64 g0=0, g1=0, q0=0, q1=0;
            #pragma unroll
            for (int p = 0; p < 8; ++p) {
                ulonglong2 sv = *(const ulonglong2*)(Srw + p*8);
                ulonglong2 a0 = *(const ulonglong2*)(Ar0 + p*8);
                ulonglong2 a1 = *(const ulonglong2*)(Ar1 + p*8);
                ulonglong2 r0 = *(const ulonglong2*)(Rr0 + p*8);
                ulonglong2 r1 = *(const ulonglong2*)(Rr1 + p*8);
                g0 = fma2(a0.x, sv.x, g0); g0 = fma2(a0.y, sv.y, g0);
                g1 = fma2(a1.x, sv.x, g1); g1 = fma2(a1.y, sv.y, g1);
                q0 = fma2(r0.x, sv.x, q0); q0 = fma2(r0.y, sv.y, q0);
                q1 = fma2(r1.x, sv.x, q1); q1 = fma2(r1.y, sv.y, q1);
            }
            float fg0 = hsum2(g0), fg1 = hsum2(g1);
            float fy0 = hsum2(q0), fy1 = hsum2(q1);
            fg0 += __shfl_xor_sync(0xffffffffu, fg0, 16);
            fg1 += __shfl_xor_sync(0xffffffffu, fg1, 16);
            fy0 += __shfl_xor_sync(0xffffffffu, fy0, 16);
            fy1 += __shfl_xor_sync(0xffffffffu, fy1, 16);
            if (jh == 0) {
                sG[tauA*17 + ii1] = fg0 + S.MV[tauA][ii1];
                sG[tauB*17 + ii1] = fg1 + S.MV[tauB][ii1];
                sY[tauA*17 + ii1] = fy0;
                sY[tauB*17 + ii1] = fy1;
            }
        }
        __syncthreads();

        // ---- U[tau][ii] = Tinv[tau,:] . G[:,ii] ----
        {
            float4 t0 = *(const float4*)&S.Ti[tauU][0];
            float4 t1 = *(const float4*)&S.Ti[tauU][4];
            float4 t2 = *(const float4*)&S.Ti[tauU][8];
            float4 t3 = *(const float4*)&S.Ti[tauU][12];
            const float* gcol = sG + ii1;
            float u;
            u = t0.x * gcol[0*17];
            u = fmaf(t0.y, gcol[1*17], u);
            u = fmaf(t0.z, gcol[2*17], u);
            u = fmaf(t0.w, gcol[3*17], u);
            u = fmaf(t1.x, gcol[4*17], u);
            u = fmaf(t1.y, gcol[5*17], u);
            u = fmaf(t1.z, gcol[6*17], u);
            u = fmaf(t1.w, gcol[7*17], u);
            u = fmaf(t2.x, gcol[8*17], u);
            u = fmaf(t2.y, gcol[9*17], u);
            u = fmaf(t2.z, gcol[10*17], u);
            u = fmaf(t2.w, gcol[11*17], u);
            u = fmaf(t3.x, gcol[12*17], u);
            u = fmaf(t3.y, gcol[13*17], u);
            u = fmaf(t3.z, gcol[14*17], u);
            u = fmaf(t3.w, gcol[15*17], u);
            sU[tauU*17 + ii1] = u;
        }
        __syncthreads();

        // ---- Y finalize ----
        {
            float yv = sY[tauU*17 + ii1] + S.RKV[tauU][ii1];
            float4 b0 = *(const float4*)&S.RBm[tauU][0];
            float4 b1 = *(const float4*)&S.RBm[tauU][4];
            float4 b2 = *(const float4*)&S.RBm[tauU][8];
            float4 b3 = *(const float4*)&S.RBm[tauU][12];
            const float* ucol = sU + ii1;
            yv = fmaf(b0.x, ucol[0*17], yv);
            yv = fmaf(b0.y, ucol[1*17], yv);
            yv = fmaf(b0.z, ucol[2*17], yv);
            yv = fmaf(b0.w, ucol[3*17], yv);
            yv = fmaf(b1.x, ucol[4*17], yv);
            yv = fmaf(b1.y, ucol[5*17], yv);
            yv = fmaf(b1.z, ucol[6*17], yv);
            yv = fmaf(b1.w, ucol[7*17], yv);
            yv = fmaf(b2.x, ucol[8*17], yv);
            yv = fmaf(b2.y, ucol[9*17], yv);
            yv = fmaf(b2.z, ucol[10*17], yv);
            yv = fmaf(b2.w, ucol[11*17], yv);
            yv = fmaf(b3.x, ucol[12*17], yv);
            yv = fmaf(b3.y, ucol[13*17], yv);
            yv = fmaf(b3.z, ucol[14*17], yv);
            yv = fmaf(b3.w, ucol[15*17], yv);
            yOut[((size_t)(c*L + tauU) * HH + h) * NN + i0 + ii1] = yv;
        }

        // ---- S update: warp's j-slice. S = wL.S + B^T U + K^T V ----
        {
            u64* srow = (u64*)&sS[ii1*68 + jb];
            const u64* wl = (const u64*)&S.wL[jb];
            const float* ucol = sU + ii1;
            u64 n0 = mul2(srow[0], wl[0]);
            u64 n1 = mul2(srow[1], wl[1]);
            #pragma unroll
            for (int s = 0; s < L; ++s) {
                u64 u2 = bcast2(ucol[s*17]);
                u64 v2 = bcast2(S.V[s][ii1]);
                ulonglong2 bv = *(const ulonglong2*)&S.Bq[s][jb];
                ulonglong2 kv = *(const ulonglong2*)&S.Kq[s][jb];
                n0 = fma2(bv.x, u2, n0); n0 = fma2(kv.x, v2, n0);
                n1 = fma2(bv.y, u2, n1); n1 = fma2(kv.y, v2, n1);
            }
            srow[0] = n0; srow[1] = n1;
        }
    }

    // ---- final state ----
    __syncthreads();
    #pragma unroll
    for (int r = 0; r < 4; ++r) {
        int idx = tid + r*256;
        int si = idx >> 6, j = idx & 63;
        sOut[((size_t)h*NN + i0 + si)*NN + j] = sS[si*68 + j];
    }
}

extern "C" void kernel_launch(void* const* d_in, const int* in_sizes, int n_in,
                              void* d_out, int out_size)
{
    const float* r  = (const float*)d_in[0];
    const float* w  = (const float*)d_in[1];
    const float* k  = (const float*)d_in[2];
    const float* v  = (const float*)d_in[3];
    const float* a  = (const float*)d_in[4];
    const float* b  = (const float*)d_in[5];
    const float* st = (const float*)d_in[6];

    const int T  = in_sizes[0] / (HH * NN);
    const int NC = T / L;

    float* y    = (float*)d_out;
    float* sfin = y + (size_t)T * HH * NN;

    const int smem2 = (3*STAGE_F + 16*68 + 3*16*17) * 4;
    cudaFuncSetAttribute(wkv7_k2, cudaFuncAttributeMaxDynamicSharedMemorySize, smem2);

    wkv7_k1<<<NC * HH, 256>>>(r, w, k, v, a, b);
    wkv7_k2<<<HH * 4, 256, smem2>>>(v, st, y, sfin, NC);
}